// round 3
// baseline (speedup 1.0000x reference)
#include <cuda_runtime.h>
#include <cstdint>

// MonarchAttention on GB300 — fp32 batched 64x64x64 GEMMs using packed
// fma.rn.f32x2 (FFMA2) with k-pair-interleaved smem operands.
// B=4,H=16 -> BH=64; N=4096, D=64, b=m=64, STEPS=3.
//
// Smem operand layout: element (k, idx) -> float offset (k>>1)*S2 + 2*idx + (k&1)
// so one 16-B load gives {evenK,oddK} b64 pairs for idx and idx+1.
//
// Global layouts (fp32):
//   Q/K/V   : [bh][blk][intra][d]
//   g_L     : [bh][s][i][j]
//   g_qbar  : [bh][j][s][d]
//   g_kbar  : [bh][s][j][d]
//   g_vbar  : [bh][s][j][d]
//   g_ent   : [bh][s][j]   g_qmean : [bh][s][d]

typedef unsigned long long ull;

#define S2    132            // floats per k-pair row (16B-aligned rows)
#define OPF   (32 * S2)      // 4224 floats = 16896 B per 64x64 operand
#define SCALE 0.125f

__device__ float g_qmean[262144];
__device__ float g_ent  [262144];
__device__ float g_L    [16777216];
__device__ float g_qbar [16777216];
__device__ float g_kbar [16777216];
__device__ float g_vbar [16777216];

// ---------------------------------------------------------------------------
__device__ __forceinline__ float redmax16(float v) {
#pragma unroll
    for (int m = 8; m; m >>= 1) v = fmaxf(v, __shfl_xor_sync(0xffffffffu, v, m));
    return v;
}
__device__ __forceinline__ float redsum16(float v) {
#pragma unroll
    for (int m = 8; m; m >>= 1) v += __shfl_xor_sync(0xffffffffu, v, m);
    return v;
}
__device__ __forceinline__ void ffma2(ull& c, ull a, ull b) {
    asm("fma.rn.f32x2 %0, %1, %2, %0;" : "+l"(c) : "l"(a), "l"(b));
}
__device__ __forceinline__ float usum(ull v) {
    float x, y;
    asm("mov.b64 {%0,%1}, %2;" : "=f"(x), "=f"(y) : "l"(v));
    return x + y;
}

// C[aidx][bidx] = sum_k A[k][aidx]*B[k][bidx], both k-pair interleaved.
__device__ __forceinline__ void mmk2(const float* __restrict__ sA,
                                     const float* __restrict__ sB,
                                     int ty4, int tx4, ull acc[4][4]) {
#pragma unroll 8
    for (int kp = 0; kp < 32; ++kp) {
        const ulonglong2* pa =
            reinterpret_cast<const ulonglong2*>(sA + kp * S2 + 2 * ty4);
        const ulonglong2* pb =
            reinterpret_cast<const ulonglong2*>(sB + kp * S2 + 2 * tx4);
        ulonglong2 a01 = pa[0], a23 = pa[1];
        ulonglong2 b01 = pb[0], b23 = pb[1];
        ull a[4] = {a01.x, a01.y, a23.x, a23.y};
        ull b[4] = {b01.x, b01.y, b23.x, b23.y};
#pragma unroll
        for (int r = 0; r < 4; ++r)
#pragma unroll
            for (int c = 0; c < 4; ++c) ffma2(acc[r][c], a[r], b[c]);
    }
}

// ---------------------------------------------------------------------------
// A0: qmean[bh][s][d] = mean_i Q[bh][i][s][d]
// ---------------------------------------------------------------------------
__global__ void qmean_kernel(const float* __restrict__ Q) {
    int bid = blockIdx.x;
    int bh = bid >> 4;
    int s = ((bid & 15) << 2) + (threadIdx.x >> 6);
    int d = threadIdx.x & 63;
    const float* base = Q + bh * 262144 + s * 64 + d;
    float acc = 0.f;
#pragma unroll 16
    for (int i = 0; i < 64; ++i) acc += base[i * 4096];
    g_qmean[(bh << 6 | s) * 64 + d] = acc * (1.0f / 64.0f);
}

// ---------------------------------------------------------------------------
// A: per (bh,s): w[j]=sum_i L[i][j]; qbar[j][d]=(sum_i L[i][j]Q[i][d])/w[j]
// ---------------------------------------------------------------------------
__global__ void qbar_kernel(const float* __restrict__ Q) {
    int bid = blockIdx.x, bh = bid >> 6, s = bid & 63;
    extern __shared__ float sm[];
    float* sL = sm;             // (k=i, idx=j)
    float* sQ = sm + OPF;       // (k=i, idx=d)
    float* sw = sm + 2 * OPF;   // [64] 1/w
    int tid = threadIdx.x;

    const float* Lb = g_L + ((bh << 6 | s) << 12);
    const float* Qb = Q + bh * 262144 + s * 64;
#pragma unroll
    for (int r = 0; r < 8; ++r) {
        int e = (r << 8) + tid;          // k-pair element index
        int kp = e >> 6, idx = e & 63;
        float2 lv = make_float2(Lb[(kp << 7) + idx], Lb[(kp << 7) + 64 + idx]);
        *reinterpret_cast<float2*>(sL + kp * S2 + 2 * idx) = lv;
        float2 qv = make_float2(Qb[(kp << 1) * 4096 + idx],
                                Qb[((kp << 1) + 1) * 4096 + idx]);
        *reinterpret_cast<float2*>(sQ + kp * S2 + 2 * idx) = qv;
    }
    __syncthreads();
    if (tid < 64) {
        float a = 0.f;
#pragma unroll 8
        for (int kp = 0; kp < 32; ++kp) {
            float2 lv = *reinterpret_cast<float2*>(sL + kp * S2 + 2 * tid);
            a += lv.x + lv.y;
        }
        sw[tid] = 1.0f / a;
    }
    __syncthreads();

    int tx = tid & 15, ty = tid >> 4;
    ull acc[4][4] = {};
    mmk2(sL, sQ, ty << 2, tx << 2, acc);

    float* ob = g_qbar + bh * 262144 + s * 64 + (tx << 2);
#pragma unroll
    for (int rr = 0; rr < 4; ++rr) {
        int j = (ty << 2) + rr;
        float w = sw[j];
        *reinterpret_cast<float4*>(ob + j * 4096) =
            make_float4(usum(acc[rr][0]) * w, usum(acc[rr][1]) * w,
                        usum(acc[rr][2]) * w, usum(acc[rr][3]) * w);
    }
}

// ---------------------------------------------------------------------------
// B: per (bh,j): S=scale*qbar_j K^T; R=softmax_t; ent; kbar=R K; (vbar=R V)
// ---------------------------------------------------------------------------
__global__ void bstep_kernel(const float* __restrict__ Kg, const float* __restrict__ Vg,
                             int use_qmean, int do_vbar) {
    int bid = blockIdx.x, bh = bid >> 6, j = bid & 63;
    extern __shared__ float sm[];
    float* sQbT = sm;             // (k=d, idx=s)
    float* sKT  = sm + OPF;       // (k=d, idx=t)
    float* sK   = sm + 2 * OPF;   // (k=t, idx=d)
    float* sV   = sm + 3 * OPF;   // (k=t, idx=d)
    float* sRT  = sm + 4 * OPF;   // (k=t, idx=s)
    int tid = threadIdx.x;

    const float* Kb = Kg + bh * 262144 + j * 4096;
    const float* qb = use_qmean ? (g_qmean + (bh << 12))
                                : (g_qbar + bh * 262144 + j * 4096);
#pragma unroll
    for (int r = 0; r < 16; ++r) {
        int lin = (r << 8) + tid;
        int row = lin >> 6, d = lin & 63;   // row = t (K) or s (qbar)
        float kv = Kb[lin];
        sKT[(d >> 1) * S2 + 2 * row + (d & 1)] = kv;
        sK [(row >> 1) * S2 + 2 * d + (row & 1)] = kv;
        sQbT[(d >> 1) * S2 + 2 * row + (d & 1)] = qb[lin];
    }
    if (do_vbar) {
        const float* Vb = Vg + bh * 262144 + j * 4096;
#pragma unroll
        for (int r = 0; r < 16; ++r) {
            int lin = (r << 8) + tid;
            int t = lin >> 6, d = lin & 63;
            sV[(t >> 1) * S2 + 2 * d + (t & 1)] = Vb[lin];
        }
    }
    __syncthreads();

    int tx = tid & 15, ty = tid >> 4;
    int tx4 = tx << 2, ty4 = ty << 2;

    ull accS[4][4] = {};
    mmk2(sQbT, sKT, ty4, tx4, accS);

    float R[4][4];
#pragma unroll
    for (int rr = 0; rr < 4; ++rr) {
        float Sv[4], mx = -1e30f;
#pragma unroll
        for (int cc = 0; cc < 4; ++cc) {
            Sv[cc] = usum(accS[rr][cc]) * SCALE;
            mx = fmaxf(mx, Sv[cc]);
        }
        mx = redmax16(mx);
        float sum = 0.f;
#pragma unroll
        for (int cc = 0; cc < 4; ++cc) { R[rr][cc] = __expf(Sv[cc] - mx); sum += R[rr][cc]; }
        sum = redsum16(sum);
        float inv = 1.0f / sum, lsum = __logf(sum), e = 0.f;
#pragma unroll
        for (int cc = 0; cc < 4; ++cc) {
            float rv = R[rr][cc] * inv;
            e += rv * (Sv[cc] - mx - lsum);
            R[rr][cc] = rv;
        }
        e = redsum16(e);
        if (tx == 0) g_ent[((bh << 6) + ty4 + rr) * 64 + j] = -e;
    }
#pragma unroll
    for (int rr = 0; rr < 4; ++rr)
#pragma unroll
        for (int cc = 0; cc < 4; ++cc) {
            int t = tx4 + cc;
            sRT[(t >> 1) * S2 + 2 * (ty4 + rr) + (t & 1)] = R[rr][cc];
        }
    __syncthreads();

    ull acc[4][4] = {};
    mmk2(sRT, sK, ty4, tx4, acc);
#pragma unroll
    for (int rr = 0; rr < 4; ++rr) {
        int s = ty4 + rr;
        *reinterpret_cast<float4*>(g_kbar + ((bh << 6 | s) << 12) + (j << 6) + tx4) =
            make_float4(usum(acc[rr][0]), usum(acc[rr][1]),
                        usum(acc[rr][2]), usum(acc[rr][3]));
    }
    if (do_vbar) {
        ull av[4][4] = {};
        mmk2(sRT, sV, ty4, tx4, av);
#pragma unroll
        for (int rr = 0; rr < 4; ++rr) {
            int s = ty4 + rr;
            *reinterpret_cast<float4*>(g_vbar + ((bh << 6 | s) << 12) + (j << 6) + tx4) =
                make_float4(usum(av[rr][0]), usum(av[rr][1]),
                            usum(av[rr][2]), usum(av[rr][3]));
        }
    }
}

// ---------------------------------------------------------------------------
// C: per (bh,s): SL = scale*Q kbar^T + ent; L=softmax_j; write L or out=L vbar
// ---------------------------------------------------------------------------
__global__ void cstep_kernel(const float* __restrict__ Qg, float* __restrict__ out,
                             int is_final) {
    int bid = blockIdx.x, bh = bid >> 6, s = bid & 63;
    extern __shared__ float sm[];
    float* sQT  = sm;             // (k=d, idx=i)
    float* sKbT = sm + OPF;       // (k=d, idx=j)
    float* sLT  = sm + 2 * OPF;   // (k=j, idx=i)  final only
    float* sVb  = sm + 3 * OPF;   // (k=j, idx=d)  final only
    float* sEnt = sm + 4 * OPF;   // [64]
    int tid = threadIdx.x;

    const float* Qb = Qg + bh * 262144 + s * 64;
    const float* kb = g_kbar + ((bh << 6 | s) << 12);
#pragma unroll
    for (int r = 0; r < 16; ++r) {
        int lin = (r << 8) + tid;
        int row = lin >> 6, d = lin & 63;   // row = i (Q) or j (kbar)
        sQT [(d >> 1) * S2 + 2 * row + (d & 1)] = Qb[row * 4096 + d];
        sKbT[(d >> 1) * S2 + 2 * row + (d & 1)] = kb[lin];
    }
    if (is_final) {
        const float* vb = g_vbar + ((bh << 6 | s) << 12);
#pragma unroll
        for (int r = 0; r < 8; ++r) {
            int e = (r << 8) + tid;
            int kp = e >> 6, idx = e & 63;
            float2 vv = make_float2(vb[(kp << 7) + idx], vb[(kp << 7) + 64 + idx]);
            *reinterpret_cast<float2*>(sVb + kp * S2 + 2 * idx) = vv;
        }
    }
    if (tid < 64) sEnt[tid] = g_ent[((bh << 6) + s) * 64 + tid];
    __syncthreads();

    int tx = tid & 15, ty = tid >> 4;
    int tx4 = tx << 2, ty4 = ty << 2;

    ull accS[4][4] = {};
    mmk2(sQT, sKbT, ty4, tx4, accS);

    float ev[4];
#pragma unroll
    for (int cc = 0; cc < 4; ++cc) ev[cc] = sEnt[tx4 + cc];

    float L[4][4];
#pragma unroll
    for (int rr = 0; rr < 4; ++rr) {
        float Sv[4], mx = -1e30f;
#pragma unroll
        for (int cc = 0; cc < 4; ++cc) {
            Sv[cc] = usum(accS[rr][cc]) * SCALE + ev[cc];
            mx = fmaxf(mx, Sv[cc]);
        }
        mx = redmax16(mx);
        float sum = 0.f;
#pragma unroll
        for (int cc = 0; cc < 4; ++cc) { L[rr][cc] = __expf(Sv[cc] - mx); sum += L[rr][cc]; }
        sum = redsum16(sum);
        float inv = 1.0f / sum;
#pragma unroll
        for (int cc = 0; cc < 4; ++cc) L[rr][cc] *= inv;
    }

    if (!is_final) {
        float* lb = g_L + ((bh << 6 | s) << 12) + tx4;
#pragma unroll
        for (int rr = 0; rr < 4; ++rr)
            *reinterpret_cast<float4*>(lb + ((ty4 + rr) << 6)) =
                make_float4(L[rr][0], L[rr][1], L[rr][2], L[rr][3]);
    } else {
#pragma unroll
        for (int rr = 0; rr < 4; ++rr)
#pragma unroll
            for (int cc = 0; cc < 4; ++cc) {
                int jj = tx4 + cc;
                sLT[(jj >> 1) * S2 + 2 * (ty4 + rr) + (jj & 1)] = L[rr][cc];
            }
        __syncthreads();
        ull acc[4][4] = {};
        mmk2(sLT, sVb, ty4, tx4, acc);
        float* ob = out + bh * 262144 + s * 64 + tx4;
#pragma unroll
        for (int rr = 0; rr < 4; ++rr)
            *reinterpret_cast<float4*>(ob + (ty4 + rr) * 4096) =
                make_float4(usum(acc[rr][0]), usum(acc[rr][1]),
                            usum(acc[rr][2]), usum(acc[rr][3]));
    }
}

// ---------------------------------------------------------------------------
extern "C" void kernel_launch(void* const* d_in, const int* in_sizes, int n_in,
                              void* d_out, int out_size) {
    const float* Q = (const float*)d_in[0];
    const float* K = (const float*)d_in[1];
    const float* V = (const float*)d_in[2];
    float* out = (float*)d_out;

    const int SM_A = (2 * OPF + 64) * 4;   // 34048
    const int SM_B = (5 * OPF) * 4;        // 84480
    const int SM_C = (4 * OPF + 64) * 4;   // 67840
    cudaFuncSetAttribute(qbar_kernel,  cudaFuncAttributeMaxDynamicSharedMemorySize, SM_A);
    cudaFuncSetAttribute(bstep_kernel, cudaFuncAttributeMaxDynamicSharedMemorySize, SM_B);
    cudaFuncSetAttribute(cstep_kernel, cudaFuncAttributeMaxDynamicSharedMemorySize, SM_C);

    // step 0 (uniform L -> qbar == per-s mean of Q)
    qmean_kernel<<<1024, 256>>>(Q);
    bstep_kernel<<<4096, 256, SM_B>>>(K, V, 1, 0);
    cstep_kernel<<<4096, 256, SM_C>>>(Q, out, 0);
    // step 1
    qbar_kernel<<<4096, 256, SM_A>>>(Q);
    bstep_kernel<<<4096, 256, SM_B>>>(K, V, 0, 0);
    cstep_kernel<<<4096, 256, SM_C>>>(Q, out, 0);
    // step 2 (B also produces vbar; C fuses final output)
    qbar_kernel<<<4096, 256, SM_A>>>(Q);
    bstep_kernel<<<4096, 256, SM_B>>>(K, V, 0, 1);
    cstep_kernel<<<4096, 256, SM_C>>>(Q, out, 1);
}

// round 4
// speedup vs baseline: 1.2298x; 1.2298x over previous
#include <cuda_runtime.h>

// MonarchAttention on GB300 — fp32 batched 64x64x64 smem GEMMs (scalar FFMA),
// qbar-update fused into cstep (L never touches HBM).
// B=4,H=16 -> BH=64; N=4096, D=64, b=m=64, STEPS=3.
//
// Layouts (fp32):
//   Q/K/V   : [bh][blk][intra][d]
//   g_qbar  : [bh][j][s][d]
//   g_kbar  : [bh][s][j][d]
//   g_vbar  : [bh][s][j][d]
//   g_ent   : [bh][s][j]
//   g_qmean : [bh][s][d]

#define SCALE 0.125f   // 1/sqrt(64)

__device__ float g_qmean[262144];
__device__ float g_ent  [262144];
__device__ float g_qbar [16777216];
__device__ float g_kbar [16777216];
__device__ float g_vbar [16777216];

// ---------------------------------------------------------------------------
__device__ __forceinline__ float redmax16(float v) {
#pragma unroll
    for (int m = 8; m; m >>= 1) v = fmaxf(v, __shfl_xor_sync(0xffffffffu, v, m));
    return v;
}
__device__ __forceinline__ float redsum16(float v) {
#pragma unroll
    for (int m = 8; m; m >>= 1) v += __shfl_xor_sync(0xffffffffu, v, m);
    return v;
}

// C[r][c] += sum_k A[k][r]*B[k][c]; both reduction-major, float4 loads.
template <int SA, int SB>
__device__ __forceinline__ void mm16(const float* __restrict__ sA,
                                     const float* __restrict__ sB,
                                     int ty4, int tx4, float acc[4][4]) {
#pragma unroll 8
    for (int k = 0; k < 64; ++k) {
        float4 av = *reinterpret_cast<const float4*>(sA + k * SA + ty4);
        float4 bv = *reinterpret_cast<const float4*>(sB + k * SB + tx4);
        const float a[4] = {av.x, av.y, av.z, av.w};
        const float b[4] = {bv.x, bv.y, bv.z, bv.w};
#pragma unroll
        for (int r = 0; r < 4; ++r)
#pragma unroll
            for (int c = 0; c < 4; ++c)
                acc[r][c] = fmaf(a[r], b[c], acc[r][c]);
    }
}

// A stride 65, scalar loads (for register-transposed scatter arrays)
__device__ __forceinline__ void mm16_sa65(const float* __restrict__ sA,
                                          const float* __restrict__ sB,
                                          int ty4, int tx4, float acc[4][4]) {
#pragma unroll 8
    for (int k = 0; k < 64; ++k) {
        const float* ap = sA + k * 65 + ty4;
        float4 bv = *reinterpret_cast<const float4*>(sB + (k << 6) + tx4);
        const float a[4] = {ap[0], ap[1], ap[2], ap[3]};
        const float b[4] = {bv.x, bv.y, bv.z, bv.w};
#pragma unroll
        for (int r = 0; r < 4; ++r)
#pragma unroll
            for (int c = 0; c < 4; ++c)
                acc[r][c] = fmaf(a[r], b[c], acc[r][c]);
    }
}

// ---------------------------------------------------------------------------
// qmean[bh][s][d] = mean_i Q[bh][i][s][d]   (step-0 qbar is j-independent)
// ---------------------------------------------------------------------------
__global__ void qmean_kernel(const float* __restrict__ Q) {
    int bid = blockIdx.x;
    int bh = bid >> 4;
    int s = ((bid & 15) << 2) + (threadIdx.x >> 6);
    int d = threadIdx.x & 63;
    const float* base = Q + bh * 262144 + s * 64 + d;
    float acc = 0.f;
#pragma unroll 16
    for (int i = 0; i < 64; ++i) acc += base[i * 4096];
    g_qmean[(bh << 6 | s) * 64 + d] = acc * (1.0f / 64.0f);
}

// ---------------------------------------------------------------------------
// B: per (bh,j): S=scale*qbar_j K^T; R=softmax_t; ent; kbar=R K; (vbar=R V)
// grid 4096, 256 thr, smem 84224B
// ---------------------------------------------------------------------------
__global__ void __launch_bounds__(256)
bstep_kernel(const float* __restrict__ Kg, const float* __restrict__ Vg,
             int use_qmean, int do_vbar) {
    int bid = blockIdx.x, bh = bid >> 6, j = bid & 63;
    extern __shared__ float sm[];
    float* sQbT = sm;             // [d][s] stride 68
    float* sKT  = sm + 4352;      // [d][t] stride 68
    float* sK   = sm + 8704;      // [t][d] stride 64
    float* sV   = sm + 12800;     // [t][d] stride 64
    float* sRT  = sm + 16896;     // [t][s] stride 65
    int tid = threadIdx.x;

    const float* Kb = Kg + bh * 262144 + j * 4096;
    const float* qb = use_qmean ? (g_qmean + (bh << 12))
                                : (g_qbar + bh * 262144 + j * 4096);
#pragma unroll
    for (int r = 0; r < 16; ++r) {
        int lin = (r << 8) + tid;
        int t = lin >> 6, d = lin & 63;
        float v = Kb[lin];
        sK[lin] = v;
        sKT[d * 68 + t] = v;
        sQbT[d * 68 + t] = qb[lin];
    }
    if (do_vbar) {
        const float* Vb = Vg + bh * 262144 + j * 4096;
#pragma unroll
        for (int r = 0; r < 4; ++r) {
            int l4 = (r << 8) + tid;
            reinterpret_cast<float4*>(sV)[l4] = reinterpret_cast<const float4*>(Vb)[l4];
        }
    }
    __syncthreads();

    int tx = tid & 15, ty = tid >> 4;
    int tx4 = tx << 2, ty4 = ty << 2;

    float S[4][4] = {};
    mm16<68, 68>(sQbT, sKT, ty4, tx4, S);

    float R[4][4];
#pragma unroll
    for (int rr = 0; rr < 4; ++rr) {
        float mx = -1e30f;
#pragma unroll
        for (int cc = 0; cc < 4; ++cc) { S[rr][cc] *= SCALE; mx = fmaxf(mx, S[rr][cc]); }
        mx = redmax16(mx);
        float sum = 0.f;
#pragma unroll
        for (int cc = 0; cc < 4; ++cc) { R[rr][cc] = __expf(S[rr][cc] - mx); sum += R[rr][cc]; }
        sum = redsum16(sum);
        float inv = 1.0f / sum, lsum = __logf(sum), e = 0.f;
#pragma unroll
        for (int cc = 0; cc < 4; ++cc) {
            float rv = R[rr][cc] * inv;
            e += rv * (S[rr][cc] - mx - lsum);
            R[rr][cc] = rv;
        }
        e = redsum16(e);
        if (tx == 0) g_ent[((bh << 6) + ty4 + rr) * 64 + j] = -e;
    }
#pragma unroll
    for (int rr = 0; rr < 4; ++rr)
#pragma unroll
        for (int cc = 0; cc < 4; ++cc)
            sRT[(tx4 + cc) * 65 + ty4 + rr] = R[rr][cc];
    __syncthreads();

    float acc[4][4] = {};
    mm16_sa65(sRT, sK, ty4, tx4, acc);
#pragma unroll
    for (int rr = 0; rr < 4; ++rr) {
        int s = ty4 + rr;
        *reinterpret_cast<float4*>(g_kbar + ((bh << 6 | s) << 12) + (j << 6) + tx4) =
            make_float4(acc[rr][0], acc[rr][1], acc[rr][2], acc[rr][3]);
    }
    if (do_vbar) {
        float av[4][4] = {};
        mm16_sa65(sRT, sV, ty4, tx4, av);
#pragma unroll
        for (int rr = 0; rr < 4; ++rr) {
            int s = ty4 + rr;
            *reinterpret_cast<float4*>(g_vbar + ((bh << 6 | s) << 12) + (j << 6) + tx4) =
                make_float4(av[rr][0], av[rr][1], av[rr][2], av[rr][3]);
        }
    }
}

// ---------------------------------------------------------------------------
// C (fused): per (bh,s):
//   SL = scale*Q kbar^T + ent;  L = softmax_j(SL)
//   non-final: w[j]=sum_i L[i][j];  qbar[j][d]=(sum_i L[i][j]Q[i][d])/w[j]
//   final:     out[i][d] = sum_j L[i][j] vbar[j][d]
// grid 4096, 256 thr, smem 85504B
// ---------------------------------------------------------------------------
__global__ void __launch_bounds__(256)
cstep_kernel(const float* __restrict__ Qg, float* __restrict__ out, int is_final) {
    int bid = blockIdx.x, bh = bid >> 6, s = bid & 63;
    extern __shared__ float sm[];
    float* sQT  = sm;             // [d][i] stride 68   (GEMM1 A)
    float* sKbT = sm + 4352;      // [d][j] stride 68   (GEMM1 B)
    float* sQ   = sm + 8704;      // [i][d] stride 64   (GEMM2 B, non-final)
    float* sLA  = sm + 12800;     // [i][j] str 68 (nf) / [j][i] str 65 (final)
    float* sVb  = sm + 17152;     // [j][d] stride 64   (final)
    float* sEnt = sm + 21248;     // [64]
    float* sW   = sm + 21312;     // [64] 1/w
    int tid = threadIdx.x;

    const float* Qb = Qg + bh * 262144 + s * 64;
    const float* kb = g_kbar + ((bh << 6 | s) << 12);
#pragma unroll
    for (int r = 0; r < 16; ++r) {
        int lin = (r << 8) + tid;
        int row = lin >> 6, d = lin & 63;   // row = i (Q) or j (kbar)
        float qv = Qb[row * 4096 + d];
        sQT[d * 68 + row] = qv;
        sQ[(row << 6) + d] = qv;
        sKbT[d * 68 + row] = kb[lin];
    }
    if (is_final) {
        const float* vb = g_vbar + ((bh << 6 | s) << 12);
#pragma unroll
        for (int r = 0; r < 4; ++r) {
            int l4 = (r << 8) + tid;
            reinterpret_cast<float4*>(sVb)[l4] = reinterpret_cast<const float4*>(vb)[l4];
        }
    }
    if (tid < 64) sEnt[tid] = g_ent[((bh << 6) + s) * 64 + tid];
    __syncthreads();

    int tx = tid & 15, ty = tid >> 4;
    int tx4 = tx << 2, ty4 = ty << 2;

    float S[4][4] = {};
    mm16<68, 68>(sQT, sKbT, ty4, tx4, S);

    float ev[4];
#pragma unroll
    for (int cc = 0; cc < 4; ++cc) ev[cc] = sEnt[tx4 + cc];

    float L[4][4];
#pragma unroll
    for (int rr = 0; rr < 4; ++rr) {
        float mx = -1e30f;
#pragma unroll
        for (int cc = 0; cc < 4; ++cc) {
            S[rr][cc] = S[rr][cc] * SCALE + ev[cc];
            mx = fmaxf(mx, S[rr][cc]);
        }
        mx = redmax16(mx);
        float sum = 0.f;
#pragma unroll
        for (int cc = 0; cc < 4; ++cc) { L[rr][cc] = __expf(S[rr][cc] - mx); sum += L[rr][cc]; }
        sum = redsum16(sum);
        float inv = 1.0f / sum;
#pragma unroll
        for (int cc = 0; cc < 4; ++cc) L[rr][cc] *= inv;
    }

    if (!is_final) {
        // scatter L as [k=i][j] stride 68 (float4-loadable for GEMM2 A)
#pragma unroll
        for (int rr = 0; rr < 4; ++rr)
#pragma unroll
            for (int cc = 0; cc < 4; ++cc)
                sLA[(ty4 + rr) * 68 + tx4 + cc] = L[rr][cc];
        __syncthreads();
        if (tid < 64) {
            float a = 0.f;
#pragma unroll 8
            for (int i = 0; i < 64; ++i) a += sLA[i * 68 + tid];
            sW[tid] = 1.0f / a;
        }
        __syncthreads();
        // qbar[j][d] = (sum_i L[i][j] Q[i][d]) / w[j]
        float acc[4][4] = {};
        mm16<68, 64>(sLA, sQ, ty4, tx4, acc);
        float* ob = g_qbar + bh * 262144 + s * 64 + tx4;
#pragma unroll
        for (int rr = 0; rr < 4; ++rr) {
            int j = ty4 + rr;
            float w = sW[j];
            *reinterpret_cast<float4*>(ob + j * 4096) =
                make_float4(acc[rr][0] * w, acc[rr][1] * w,
                            acc[rr][2] * w, acc[rr][3] * w);
        }
    } else {
        // out[i][d] = sum_j L[i][j] vbar[j][d]   (L^T scatter, stride 65)
#pragma unroll
        for (int rr = 0; rr < 4; ++rr)
#pragma unroll
            for (int cc = 0; cc < 4; ++cc)
                sLA[(tx4 + cc) * 65 + ty4 + rr] = L[rr][cc];
        __syncthreads();
        float acc[4][4] = {};
        mm16_sa65(sLA, sVb, ty4, tx4, acc);
        float* ob = out + bh * 262144 + s * 64 + tx4;
#pragma unroll
        for (int rr = 0; rr < 4; ++rr)
            *reinterpret_cast<float4*>(ob + (ty4 + rr) * 4096) =
                make_float4(acc[rr][0], acc[rr][1], acc[rr][2], acc[rr][3]);
    }
}

// ---------------------------------------------------------------------------
extern "C" void kernel_launch(void* const* d_in, const int* in_sizes, int n_in,
                              void* d_out, int out_size) {
    const float* Q = (const float*)d_in[0];
    const float* K = (const float*)d_in[1];
    const float* V = (const float*)d_in[2];
    float* out = (float*)d_out;

    const int SM_B = 21056 * 4;   // 84224
    const int SM_C = 21376 * 4;   // 85504
    cudaFuncSetAttribute(bstep_kernel, cudaFuncAttributeMaxDynamicSharedMemorySize, SM_B);
    cudaFuncSetAttribute(cstep_kernel, cudaFuncAttributeMaxDynamicSharedMemorySize, SM_C);

    // step 0 (uniform L -> qbar == per-s mean of Q)
    qmean_kernel<<<1024, 256>>>(Q);
    bstep_kernel<<<4096, 256, SM_B>>>(K, V, 1, 0);
    cstep_kernel<<<4096, 256, SM_C>>>(Q, out, 0);   // L-update + qbar for step 1
    // step 1
    bstep_kernel<<<4096, 256, SM_B>>>(K, V, 0, 0);
    cstep_kernel<<<4096, 256, SM_C>>>(Q, out, 0);   // L-update + qbar for step 2
    // step 2
    bstep_kernel<<<4096, 256, SM_B>>>(K, V, 0, 1);  // also vbar
    cstep_kernel<<<4096, 256, SM_C>>>(Q, out, 1);   // final: out = L vbar
}